// round 15
// baseline (speedup 1.0000x reference)
#include <cuda_runtime.h>
#include <cuda_fp16.h>
#include <math.h>
#include <stdint.h>

#define NB 2
#define NS 2048
#define ND 1024
#define NH 16
#define NDK 64
#define NM (NB*NS)   // 4096

// Scratch (allocation-free)
__device__ __half g_q[(size_t)NM * ND];
__device__ __half g_k[(size_t)NM * ND];
__device__ __half g_v[(size_t)NM * ND];
__device__ __half g_attn[(size_t)NM * ND];
__device__ __half g_xh[(size_t)NM * ND];        // x, fp16, k-pair-permuted
__device__ __half g_wh[4 * (size_t)ND * ND];    // W^T, fp16, k-pair-permuted
__device__ float2 g_rs[(size_t)NS * 512];       // (cos,sin) per (spos, pair)

#define HONES  0x3C003C00u                      // half2 {1.0, 1.0}
#define QSCALE 0.1803368801111204f              // 0.125 * log2(e)

__device__ __forceinline__ uint32_t packh2(float lo, float hi)
{
    uint32_t r;
    asm("cvt.rn.f16x2.f32 %0, %1, %2;" : "=r"(r) : "f"(hi), "f"(lo));
    return r;
}

__device__ __forceinline__ uint32_t h2ex2(uint32_t x)
{
    uint32_t r;
    asm("ex2.approx.f16x2 %0, %1;" : "=r"(r) : "r"(x));
    return r;
}

__device__ __forceinline__ void mma_f16(float& d0, float& d1, float& d2, float& d3,
                                        uint32_t a0, uint32_t a1, uint32_t a2, uint32_t a3,
                                        uint32_t b0, uint32_t b1)
{
    asm volatile(
        "mma.sync.aligned.m16n8k16.row.col.f32.f16.f16.f32 "
        "{%0,%1,%2,%3}, {%4,%5,%6,%7}, {%8,%9}, {%0,%1,%2,%3};"
        : "+f"(d0), "+f"(d1), "+f"(d2), "+f"(d3)
        : "r"(a0), "r"(a1), "r"(a2), "r"(a3), "r"(b0), "r"(b1));
}

__device__ __forceinline__ void cp_async16(void* smem_dst, const void* gsrc)
{
    uint32_t s = (uint32_t)__cvta_generic_to_shared(smem_dst);
    asm volatile("cp.async.cg.shared.global [%0], [%1], 16;" :: "r"(s), "l"(gsrc));
}
__device__ __forceinline__ void cp_commit() { asm volatile("cp.async.commit_group;"); }
__device__ __forceinline__ void cp_wait1()  { asm volatile("cp.async.wait_group 1;"); }
__device__ __forceinline__ void cp_wait2()  { asm volatile("cp.async.wait_group 2;"); }

__device__ __forceinline__ uint32_t smem_u32(const void* p)
{
    uint32_t a;
    asm("{ .reg .u64 t; cvta.to.shared.u64 t, %1; cvt.u32.u64 %0, t; }" : "=r"(a) : "l"(p));
    return a;
}

__device__ __forceinline__ void ldmatrix_x4_t(uint32_t& r0, uint32_t& r1,
                                              uint32_t& r2, uint32_t& r3, uint32_t addr)
{
    asm volatile("ldmatrix.sync.aligned.m8n8.x4.trans.shared.b16 {%0, %1, %2, %3}, [%4];"
                 : "=r"(r0), "=r"(r1), "=r"(r2), "=r"(r3) : "r"(addr));
}

// ---------------------------------------------------------------------------
// Fused prep (one launch): x->fp16-permuted | 4x W transpose+cvt+permute | rope table
// ---------------------------------------------------------------------------
#define PREP_CVT_BLOCKS   1024
#define PREP_TW_BLOCKS    4096
#define PREP_RT_BLOCKS    4096
#define PREP_BLOCKS       (PREP_CVT_BLOCKS + PREP_TW_BLOCKS + PREP_RT_BLOCKS)

__global__ void prep_kernel(const float* __restrict__ x,
                            const float* w0, const float* w1,
                            const float* w2, const float* w3)
{
    __shared__ float t[32][33];
    const int bid = blockIdx.x;
    const int tid = threadIdx.x;

    if (bid < PREP_CVT_BLOCKS) {
        size_t i = ((size_t)bid * 256 + tid) * 16;
        float4 f0 = *(const float4*)(x + i);
        float4 f1 = *(const float4*)(x + i + 4);
        float4 f2 = *(const float4*)(x + i + 8);
        float4 f3 = *(const float4*)(x + i + 12);
        uint32_t o[8];
        o[0] = packh2(f0.x, f0.y);  o[1] = packh2(f2.x, f2.y);
        o[2] = packh2(f0.z, f0.w);  o[3] = packh2(f2.z, f2.w);
        o[4] = packh2(f1.x, f1.y);  o[5] = packh2(f3.x, f3.y);
        o[6] = packh2(f1.z, f1.w);  o[7] = packh2(f3.z, f3.w);
        *(uint4*)(&g_xh[i])     = make_uint4(o[0], o[1], o[2], o[3]);
        *(uint4*)(&g_xh[i + 8]) = make_uint4(o[4], o[5], o[6], o[7]);
    } else if (bid < PREP_CVT_BLOCKS + PREP_TW_BLOCKS) {
        int idx = bid - PREP_CVT_BLOCKS;
        int bx = idx & 31, by = (idx >> 5) & 31, bz = idx >> 10;
        const float* in = (bz == 0) ? w0 : (bz == 1) ? w1 : (bz == 2) ? w2 : w3;
        __half* outp = g_wh + (size_t)bz * ND * ND;
        int tx = tid & 31, ty = tid >> 5;
        int xg = bx * 32 + tx;
        int y0 = by * 32;
        #pragma unroll
        for (int i = ty; i < 32; i += 8)
            t[i][tx] = in[(size_t)(y0 + i) * ND + xg];
        __syncthreads();
        int ox = y0 + tx;
        int w16 = ox & 15, p = w16 >> 1, par = w16 & 1;
        int pox = (ox & ~15) | (((((p & 3) << 1) | (p >> 2)) << 1) | par);
        int oy0 = bx * 32;
        #pragma unroll
        for (int i = ty; i < 32; i += 8)
            outp[(size_t)(oy0 + i) * ND + pox] = __float2half_rn(t[tx][i]);
    } else {
        int i = (bid - PREP_CVT_BLOCKS - PREP_TW_BLOCKS) * 256 + tid;
        int spos = i >> 9, pr = i & 511;
        float freq = (float)exp(((double)(-2 * pr) / (double)ND) * 9.210340371976184);
        float ang = (float)spos * freq;
        double sd, cd;
        sincos((double)ang, &sd, &cd);
        g_rs[i] = make_float2((float)cd, (float)sd);
    }
}

// ---------------------------------------------------------------------------
// fp16 GEMM v2: 128 threads, 4 warps, warp tile 64x64 (deep HMMA ILP).
// CTA tile 128x128, k-chunk 32, 4-stage cp.async ring, smem stride 48 halves
// (fragment LDS.64 conflict-free).
// Epilogue: wslot==0, zsel<2 -> RoPE + permuted fp16; zsel==2 -> natural fp16;
// wslot==3 -> float output.
// ---------------------------------------------------------------------------
#define GST 48                      // halves per row
#define GAH (128*GST)               // 6144 halves: A stage
#define GSTAGE (2*GAH)              // 12288 halves per stage (A+B)
#define GEMM_SMEM (4 * GSTAGE * 2)  // 98304 bytes

__global__ __launch_bounds__(128, 2)
void gemm_f16(const __half* __restrict__ A, int wslot,
              void* C0, void* C1, void* C2)
{
    extern __shared__ __half gsmh[];

    const int tid = threadIdx.x;
    const int warp = tid >> 5, lane = tid & 31;
    const int g = lane >> 2, tg = lane & 3;
    const int wm = (warp >> 1) << 6;   // 0 or 64
    const int wn = (warp & 1) << 6;    // 0 or 64

    const int zsel = blockIdx.z;
    void* C = (zsel == 0) ? C0 : (zsel == 1) ? C1 : C2;
    const __half* Wt = g_wh + (size_t)(wslot + zsel) * ND * ND;
    const __half* Ab = A + (size_t)(blockIdx.y * 128) * ND;
    const __half* Bb = Wt + (size_t)(blockIdx.x * 128) * ND;

    float acc[4][8][4];
    #pragma unroll
    for (int mi = 0; mi < 4; mi++)
        #pragma unroll
        for (int ni = 0; ni < 8; ni++)
            #pragma unroll
            for (int r = 0; r < 4; r++) acc[mi][ni][r] = 0.0f;

    auto PREF = [&](int stage, int k0) {
        __half* As = gsmh + stage * GSTAGE;
        __half* Bs = As + GAH;
        const __half* ap = Ab + (size_t)tid * ND + k0;
        const __half* bp = Bb + (size_t)tid * ND + k0;
        #pragma unroll
        for (int p = 0; p < 4; p++)
            cp_async16(&As[tid * GST + p * 8], ap + p * 8);
        #pragma unroll
        for (int p = 0; p < 4; p++)
            cp_async16(&Bs[tid * GST + p * 8], bp + p * 8);
        cp_commit();
    };

    PREF(0, 0); PREF(1, 32); PREF(2, 64);

    const int NKI = ND / 32;   // 32
    for (int i = 0; i < NKI; i++) {
        cp_wait2();
        __syncthreads();
        if (i + 3 < NKI) PREF((i + 3) & 3, (i + 3) * 32);

        const __half* As = gsmh + (i & 3) * GSTAGE;
        const __half* Bs = As + GAH;
        #pragma unroll
        for (int c = 0; c < 2; c++) {
            uint32_t af[4][4], bf[8][2];
            #pragma unroll
            for (int mi = 0; mi < 4; mi++) {
                uint2 lo = *(const uint2*)(&As[(wm + mi * 16 + g) * GST + c * 16 + 4 * tg]);
                uint2 hi = *(const uint2*)(&As[(wm + mi * 16 + g + 8) * GST + c * 16 + 4 * tg]);
                af[mi][0] = lo.x;  af[mi][2] = lo.y;
                af[mi][1] = hi.x;  af[mi][3] = hi.y;
            }
            #pragma unroll
            for (int ni = 0; ni < 8; ni++) {
                uint2 bb = *(const uint2*)(&Bs[(wn + ni * 8 + g) * GST + c * 16 + 4 * tg]);
                bf[ni][0] = bb.x;  bf[ni][1] = bb.y;
            }
            #pragma unroll
            for (int mi = 0; mi < 4; mi++)
                #pragma unroll
                for (int ni = 0; ni < 8; ni++)
                    mma_f16(acc[mi][ni][0], acc[mi][ni][1], acc[mi][ni][2], acc[mi][ni][3],
                            af[mi][0], af[mi][1], af[mi][2], af[mi][3],
                            bf[ni][0], bf[ni][1]);
        }
        __syncthreads();
    }

    const bool dorot = (wslot == 0 && zsel < 2);
    const float scl = (zsel == 0) ? QSCALE : 1.0f;

    #pragma unroll
    for (int mi = 0; mi < 4; mi++) {
        int r0 = blockIdx.y * 128 + wm + mi * 16 + g;
        int s0 = r0 & (NS - 1), s1 = (r0 + 8) & (NS - 1);
        #pragma unroll
        for (int ni = 0; ni < 8; ni++) {
            int col = blockIdx.x * 128 + wn + ni * 8 + tg * 2;
            float a0 = acc[mi][ni][0], a1 = acc[mi][ni][1];
            float a2 = acc[mi][ni][2], a3 = acc[mi][ni][3];
            if (wslot == 3) {
                float* Cf = (float*)C;
                *(float2*)(Cf + (size_t)r0 * ND + col)       = make_float2(a0, a1);
                *(float2*)(Cf + (size_t)(r0 + 8) * ND + col) = make_float2(a2, a3);
            } else if (dorot) {
                int pr = col >> 1;
                float2 t0 = g_rs[(size_t)s0 * 512 + pr];
                float2 t1 = g_rs[(size_t)s1 * 512 + pr];
                float n0 = (a0 * t0.x - a1 * t0.y) * scl;
                float n1 = (a0 * t0.y + a1 * t0.x) * scl;
                float n2 = (a2 * t1.x - a3 * t1.y) * scl;
                float n3 = (a2 * t1.y + a3 * t1.x) * scl;
                int p16 = pr & 7;
                int pp = ((p16 & 3) << 1) | (p16 >> 2);
                int wcol = (col & ~15) + 2 * pp;
                __half* Ch = (__half*)C;
                *(uint32_t*)(Ch + (size_t)r0 * ND + wcol)       = packh2(n0, n1);
                *(uint32_t*)(Ch + (size_t)(r0 + 8) * ND + wcol) = packh2(n2, n3);
            } else {   // V: natural fp16
                __half* Ch = (__half*)C;
                *(uint32_t*)(Ch + (size_t)r0 * ND + col)       = packh2(a0, a1);
                *(uint32_t*)(Ch + (size_t)(r0 + 8) * ND + col) = packh2(a2, a3);
            }
        }
    }
}

// ---------------------------------------------------------------------------
// Flash attention (unchanged): fp16 mma, no max-tracking, base-2 logits,
// 3-stage KV ring, P = ex2.f16x2(S), l via ones-column MMA, V ldmatrix.x4.trans
// ---------------------------------------------------------------------------
#define FQ  10240                  // halves: Q 128*80
#define FKB 5120                   // halves: K stage 64*80
#define FVB 4608                   // halves: V stage 64*72
#define FLASH_SMEM ((FQ + 3 * FKB + 3 * FVB) * 2)   // 78848 bytes

extern __shared__ __half fsh[];

__global__ __launch_bounds__(256, 2)
void flash_f16(const __half* __restrict__ Q, const __half* __restrict__ K,
               const __half* __restrict__ V, __half* __restrict__ O)
{
    __half* Qs  = fsh;
    __half* Ksb = fsh + FQ;
    __half* Vsb = fsh + FQ + 3 * FKB;

    const int tid = threadIdx.x;
    const int warp = tid >> 5, lane = tid & 31;
    const int g = lane >> 2, tg = lane & 3;
    const int qt = (int)gridDim.x - 1 - (int)blockIdx.x;
    const int bh = blockIdx.y;
    const int b = bh >> 4, h = bh & 15;
    const size_t base = (size_t)b * NS * ND + (size_t)h * NDK;
    const int q0 = qt * 128;
    const int wm = warp * 16;

    const int rq = tid >> 1, cq = (tid & 1) * 4;
    const int rk = tid >> 2, ck = (tid & 3) * 2;

    auto PREFKV = [&](int stage, int t) {
        __half* Ks = Ksb + stage * FKB;
        __half* Vs = Vsb + stage * FVB;
        int kn = 64 * t;
        #pragma unroll
        for (int p = 0; p < 2; p++) {
            cp_async16(&Ks[rk * 80 + (ck + p) * 8],
                       K + base + (size_t)(kn + rk) * ND + (ck + p) * 8);
            cp_async16(&Vs[rk * 72 + (ck + p) * 8],
                       V + base + (size_t)(kn + rk) * ND + (ck + p) * 8);
        }
        cp_commit();
    };

    #pragma unroll
    for (int p = 0; p < 4; p++)
        cp_async16(&Qs[rq * 80 + (cq + p) * 8],
                   Q + base + (size_t)(q0 + rq) * ND + (cq + p) * 8);
    {
        __half* Ks = Ksb; __half* Vs = Vsb;
        #pragma unroll
        for (int p = 0; p < 2; p++) {
            cp_async16(&Ks[rk * 80 + (ck + p) * 8],
                       K + base + (size_t)rk * ND + (ck + p) * 8);
            cp_async16(&Vs[rk * 72 + (ck + p) * 8],
                       V + base + (size_t)rk * ND + (ck + p) * 8);
        }
        cp_commit();
    }
    PREFKV(1, 1);

    const uint32_t vbase = smem_u32(Vsb) + (lane & 15) * 144 + (lane >> 4) * 16;

    float lacc[4] = {0.0f, 0.0f, 0.0f, 0.0f};
    float of[8][4];
    #pragma unroll
    for (int f = 0; f < 8; f++)
        #pragma unroll
        for (int rr = 0; rr < 4; rr++) of[f][rr] = 0.0f;

    uint32_t qf[4][4];

    const int nt = 2 * qt + 2;
    int stage = 0;
    for (int t = 0; t < nt; t++) {
        cp_wait1();
        __syncthreads();

        if (t == 0) {
            #pragma unroll
            for (int c = 0; c < 4; c++) {
                uint2 qlo = *(const uint2*)(&Qs[(wm + g) * 80 + c * 16 + 4 * tg]);
                uint2 qhi = *(const uint2*)(&Qs[(wm + g + 8) * 80 + c * 16 + 4 * tg]);
                qf[c][0] = qlo.x;  qf[c][2] = qlo.y;
                qf[c][1] = qhi.x;  qf[c][3] = qhi.y;
            }
        }

        if (t + 2 < nt) {
            int ns = stage + 2; if (ns >= 3) ns -= 3;
            PREFKV(ns, t + 2);
        }

        const __half* Kc = Ksb + stage * FKB;
        const int k0 = 64 * t;

        float sf[8][4];
        #pragma unroll
        for (int f = 0; f < 8; f++)
            #pragma unroll
            for (int rr = 0; rr < 4; rr++) sf[f][rr] = 0.0f;

        #pragma unroll
        for (int c = 0; c < 4; c++) {
            #pragma unroll
            for (int f = 0; f < 8; f++) {
                uint2 kb = *(const uint2*)(&Kc[(f * 8 + g) * 80 + c * 16 + 4 * tg]);
                mma_f16(sf[f][0], sf[f][1], sf[f][2], sf[f][3],
                        qf[c][0], qf[c][1], qf[c][2], qf[c][3], kb.x, kb.y);
            }
        }

        if (t >= 2 * qt) {
            int rlo = q0 + wm + g, rhi = rlo + 8;
            #pragma unroll
            for (int f = 0; f < 8; f++) {
                int col = k0 + f * 8 + tg * 2;
                if (col     > rlo) sf[f][0] = -INFINITY;
                if (col + 1 > rlo) sf[f][1] = -INFINITY;
                if (col     > rhi) sf[f][2] = -INFINITY;
                if (col + 1 > rhi) sf[f][3] = -INFINITY;
            }
        }

        const uint32_t vb = vbase + stage * (FVB * 2);
        #pragma unroll
        for (int c = 0; c < 4; c++) {
            uint32_t a0 = h2ex2(packh2(sf[2 * c][0],     sf[2 * c][1]));
            uint32_t a1 = h2ex2(packh2(sf[2 * c][2],     sf[2 * c][3]));
            uint32_t a2 = h2ex2(packh2(sf[2 * c + 1][0], sf[2 * c + 1][1]));
            uint32_t a3 = h2ex2(packh2(sf[2 * c + 1][2], sf[2 * c + 1][3]));
            mma_f16(lacc[0], lacc[1], lacc[2], lacc[3],
                    a0, a1, a2, a3, HONES, HONES);
            #pragma unroll
            for (int f2 = 0; f2 < 4; f2++) {
                uint32_t b00, b01, b10, b11;
                ldmatrix_x4_t(b00, b01, b10, b11, vb + c * 2304 + f2 * 32);
                mma_f16(of[2 * f2][0], of[2 * f2][1], of[2 * f2][2], of[2 * f2][3],
                        a0, a1, a2, a3, b00, b01);
                mma_f16(of[2 * f2 + 1][0], of[2 * f2 + 1][1],
                        of[2 * f2 + 1][2], of[2 * f2 + 1][3],
                        a0, a1, a2, a3, b10, b11);
            }
        }
        stage++; if (stage == 3) stage = 0;
    }

    float i0 = 1.0f / lacc[0], i1 = 1.0f / lacc[2];
    int rlo = q0 + wm + g;
    #pragma unroll
    for (int f = 0; f < 8; f++) {
        int pos = (f >> 1) * 16 + ((f & 1) ? 4 * tg + 2 : 4 * tg);
        *(uint32_t*)(O + base + (size_t)rlo * ND + pos) =
            packh2(of[f][0] * i0, of[f][1] * i0);
        *(uint32_t*)(O + base + (size_t)(rlo + 8) * ND + pos) =
            packh2(of[f][2] * i1, of[f][3] * i1);
    }
}

// ---------------------------------------------------------------------------
extern "C" void kernel_launch(void* const* d_in, const int* in_sizes, int n_in,
                              void* d_out, int out_size)
{
    const float* x  = (const float*)d_in[0];
    const float* Wq = (const float*)d_in[1];
    const float* Wk = (const float*)d_in[2];
    const float* Wv = (const float*)d_in[3];
    const float* Wo = (const float*)d_in[4];
    float* out = (float*)d_out;

    __half *pq, *pk, *pv, *pa, *pxh;
    cudaGetSymbolAddress((void**)&pq, g_q);
    cudaGetSymbolAddress((void**)&pk, g_k);
    cudaGetSymbolAddress((void**)&pv, g_v);
    cudaGetSymbolAddress((void**)&pa, g_attn);
    cudaGetSymbolAddress((void**)&pxh, g_xh);

    cudaFuncSetAttribute(gemm_f16, cudaFuncAttributeMaxDynamicSharedMemorySize, GEMM_SMEM);
    cudaFuncSetAttribute(flash_f16, cudaFuncAttributeMaxDynamicSharedMemorySize, FLASH_SMEM);

    prep_kernel<<<PREP_BLOCKS, 256>>>(x, Wq, Wk, Wv, Wo);

    // QKV fused (rope applied in epilogue for z=0,1; V natural)
    gemm_f16<<<dim3(8, 32, 3), 128, GEMM_SMEM>>>(pxh, 0, pq, pk, pv);

    flash_f16<<<dim3(NS / 128, NB * NH), 256, FLASH_SMEM>>>(pq, pk, pv, pa);

    // Output projection: float output
    gemm_f16<<<dim3(8, 32, 1), 128, GEMM_SMEM>>>(pa, 3, out, out, out);
}

// round 16
// speedup vs baseline: 1.1857x; 1.1857x over previous
#include <cuda_runtime.h>
#include <cuda_fp16.h>
#include <math.h>
#include <stdint.h>

#define NB 2
#define NS 2048
#define ND 1024
#define NH 16
#define NDK 64
#define NM (NB*NS)   // 4096

// Scratch (allocation-free)
__device__ __half g_q[(size_t)NM * ND];
__device__ __half g_k[(size_t)NM * ND];
__device__ __half g_v[(size_t)NM * ND];
__device__ __half g_attn[(size_t)NM * ND];
__device__ __half g_xh[(size_t)NM * ND];        // x, fp16, k-pair-permuted
__device__ __half g_wh[4 * (size_t)ND * ND];    // W^T, fp16, k-pair-permuted
__device__ float2 g_rs[(size_t)NS * 512];       // (cos,sin) per (spos, pair)

#define HONES  0x3C003C00u                      // half2 {1.0, 1.0}
#define QSCALE 0.1803368801111204f              // 0.125 * log2(e)

__device__ __forceinline__ uint32_t packh2(float lo, float hi)
{
    uint32_t r;
    asm("cvt.rn.f16x2.f32 %0, %1, %2;" : "=r"(r) : "f"(hi), "f"(lo));
    return r;
}

__device__ __forceinline__ uint32_t h2ex2(uint32_t x)
{
    uint32_t r;
    asm("ex2.approx.f16x2 %0, %1;" : "=r"(r) : "r"(x));
    return r;
}

__device__ __forceinline__ void mma_f16(float& d0, float& d1, float& d2, float& d3,
                                        uint32_t a0, uint32_t a1, uint32_t a2, uint32_t a3,
                                        uint32_t b0, uint32_t b1)
{
    asm volatile(
        "mma.sync.aligned.m16n8k16.row.col.f32.f16.f16.f32 "
        "{%0,%1,%2,%3}, {%4,%5,%6,%7}, {%8,%9}, {%0,%1,%2,%3};"
        : "+f"(d0), "+f"(d1), "+f"(d2), "+f"(d3)
        : "r"(a0), "r"(a1), "r"(a2), "r"(a3), "r"(b0), "r"(b1));
}

__device__ __forceinline__ void cp_async16(void* smem_dst, const void* gsrc)
{
    uint32_t s = (uint32_t)__cvta_generic_to_shared(smem_dst);
    asm volatile("cp.async.cg.shared.global [%0], [%1], 16;" :: "r"(s), "l"(gsrc));
}
__device__ __forceinline__ void cp_commit() { asm volatile("cp.async.commit_group;"); }
__device__ __forceinline__ void cp_wait1()  { asm volatile("cp.async.wait_group 1;"); }
__device__ __forceinline__ void cp_wait2()  { asm volatile("cp.async.wait_group 2;"); }

__device__ __forceinline__ uint32_t smem_u32(const void* p)
{
    uint32_t a;
    asm("{ .reg .u64 t; cvta.to.shared.u64 t, %1; cvt.u32.u64 %0, t; }" : "=r"(a) : "l"(p));
    return a;
}

__device__ __forceinline__ void ldmatrix_x4_t(uint32_t& r0, uint32_t& r1,
                                              uint32_t& r2, uint32_t& r3, uint32_t addr)
{
    asm volatile("ldmatrix.sync.aligned.m8n8.x4.trans.shared.b16 {%0, %1, %2, %3}, [%4];"
                 : "=r"(r0), "=r"(r1), "=r"(r2), "=r"(r3) : "r"(addr));
}

// ---------------------------------------------------------------------------
// Fused prep (one launch): x->fp16-permuted | 4x W transpose+cvt+permute | rope table
// ---------------------------------------------------------------------------
#define PREP_CVT_BLOCKS   1024
#define PREP_TW_BLOCKS    4096
#define PREP_RT_BLOCKS    4096
#define PREP_BLOCKS       (PREP_CVT_BLOCKS + PREP_TW_BLOCKS + PREP_RT_BLOCKS)

__global__ void prep_kernel(const float* __restrict__ x,
                            const float* w0, const float* w1,
                            const float* w2, const float* w3)
{
    __shared__ float t[32][33];
    const int bid = blockIdx.x;
    const int tid = threadIdx.x;

    if (bid < PREP_CVT_BLOCKS) {
        size_t i = ((size_t)bid * 256 + tid) * 16;
        float4 f0 = *(const float4*)(x + i);
        float4 f1 = *(const float4*)(x + i + 4);
        float4 f2 = *(const float4*)(x + i + 8);
        float4 f3 = *(const float4*)(x + i + 12);
        uint32_t o[8];
        o[0] = packh2(f0.x, f0.y);  o[1] = packh2(f2.x, f2.y);
        o[2] = packh2(f0.z, f0.w);  o[3] = packh2(f2.z, f2.w);
        o[4] = packh2(f1.x, f1.y);  o[5] = packh2(f3.x, f3.y);
        o[6] = packh2(f1.z, f1.w);  o[7] = packh2(f3.z, f3.w);
        *(uint4*)(&g_xh[i])     = make_uint4(o[0], o[1], o[2], o[3]);
        *(uint4*)(&g_xh[i + 8]) = make_uint4(o[4], o[5], o[6], o[7]);
    } else if (bid < PREP_CVT_BLOCKS + PREP_TW_BLOCKS) {
        int idx = bid - PREP_CVT_BLOCKS;
        int bx = idx & 31, by = (idx >> 5) & 31, bz = idx >> 10;
        const float* in = (bz == 0) ? w0 : (bz == 1) ? w1 : (bz == 2) ? w2 : w3;
        __half* outp = g_wh + (size_t)bz * ND * ND;
        int tx = tid & 31, ty = tid >> 5;
        int xg = bx * 32 + tx;
        int y0 = by * 32;
        #pragma unroll
        for (int i = ty; i < 32; i += 8)
            t[i][tx] = in[(size_t)(y0 + i) * ND + xg];
        __syncthreads();
        int ox = y0 + tx;
        int w16 = ox & 15, p = w16 >> 1, par = w16 & 1;
        int pox = (ox & ~15) | (((((p & 3) << 1) | (p >> 2)) << 1) | par);
        int oy0 = bx * 32;
        #pragma unroll
        for (int i = ty; i < 32; i += 8)
            outp[(size_t)(oy0 + i) * ND + pox] = __float2half_rn(t[tx][i]);
    } else {
        int i = (bid - PREP_CVT_BLOCKS - PREP_TW_BLOCKS) * 256 + tid;
        int spos = i >> 9, pr = i & 511;
        float freq = (float)exp(((double)(-2 * pr) / (double)ND) * 9.210340371976184);
        float ang = (float)spos * freq;
        double sd, cd;
        sincos((double)ang, &sd, &cd);
        g_rs[i] = make_float2((float)cd, (float)sd);
    }
}

// ---------------------------------------------------------------------------
// fp16 GEMM (R14 shape: 256 thr, 8 warps of 64x32), k-chunk 32, 4-stage ring,
// stride 48 halves (conflict-free). Changes vs R14:
//   - single barrier per chunk (end-of-loop sync removed; top sync covers WAR)
//   - B-frags loaded first, then per-mi {2 LDS -> 4 MMA} for LDS/MMA overlap
// Epilogue: wslot==0, zsel<2 -> RoPE + permuted fp16; zsel==2 -> natural fp16;
// wslot==3 -> float output.
// ---------------------------------------------------------------------------
#define GST 48                      // halves per row
#define GAH (128*GST)               // 6144 halves: A stage
#define GSTAGE (2*GAH)              // 12288 halves per stage (A+B)
#define GEMM_SMEM (4 * GSTAGE * 2)  // 98304 bytes

__global__ __launch_bounds__(256, 2)
void gemm_f16(const __half* __restrict__ A, int wslot,
              void* C0, void* C1, void* C2)
{
    extern __shared__ __half gsmh[];

    const int tid = threadIdx.x;
    const int warp = tid >> 5, lane = tid & 31;
    const int g = lane >> 2, tg = lane & 3;
    const int wm = (warp >> 2) << 6;   // 0 or 64
    const int wn = (warp & 3) << 5;    // 0,32,64,96

    const int zsel = blockIdx.z;
    void* C = (zsel == 0) ? C0 : (zsel == 1) ? C1 : C2;
    const __half* Wt = g_wh + (size_t)(wslot + zsel) * ND * ND;
    const __half* Ab = A + (size_t)(blockIdx.y * 128) * ND;
    const __half* Bb = Wt + (size_t)(blockIdx.x * 128) * ND;

    float acc[4][4][4];
    #pragma unroll
    for (int mi = 0; mi < 4; mi++)
        #pragma unroll
        for (int ni = 0; ni < 4; ni++)
            #pragma unroll
            for (int r = 0; r < 4; r++) acc[mi][ni][r] = 0.0f;

    const int lr = tid >> 1;              // 0..127
    const int lq = (tid & 1) * 16;        // half offset within 32-half chunk

    auto PREF = [&](int stage, int k0) {
        __half* As = gsmh + stage * GSTAGE;
        __half* Bs = As + GAH;
        cp_async16(&As[lr * GST + lq],     Ab + (size_t)lr * ND + k0 + lq);
        cp_async16(&As[lr * GST + lq + 8], Ab + (size_t)lr * ND + k0 + lq + 8);
        cp_async16(&Bs[lr * GST + lq],     Bb + (size_t)lr * ND + k0 + lq);
        cp_async16(&Bs[lr * GST + lq + 8], Bb + (size_t)lr * ND + k0 + lq + 8);
        cp_commit();
    };

    PREF(0, 0); PREF(1, 32); PREF(2, 64);

    const int NKI = ND / 32;   // 32
    for (int i = 0; i < NKI; i++) {
        cp_wait2();
        __syncthreads();   // single barrier/chunk: orders prior reads before PREF
        if (i + 3 < NKI) PREF((i + 3) & 3, (i + 3) * 32);

        const __half* As = gsmh + (i & 3) * GSTAGE;
        const __half* Bs = As + GAH;
        #pragma unroll
        for (int c = 0; c < 2; c++) {
            uint32_t bf[4][2];
            #pragma unroll
            for (int ni = 0; ni < 4; ni++) {
                uint2 bb = *(const uint2*)(&Bs[(wn + ni * 8 + g) * GST + c * 16 + 4 * tg]);
                bf[ni][0] = bb.x;  bf[ni][1] = bb.y;
            }
            #pragma unroll
            for (int mi = 0; mi < 4; mi++) {
                uint2 lo = *(const uint2*)(&As[(wm + mi * 16 + g) * GST + c * 16 + 4 * tg]);
                uint2 hi = *(const uint2*)(&As[(wm + mi * 16 + g + 8) * GST + c * 16 + 4 * tg]);
                #pragma unroll
                for (int ni = 0; ni < 4; ni++)
                    mma_f16(acc[mi][ni][0], acc[mi][ni][1], acc[mi][ni][2], acc[mi][ni][3],
                            lo.x, hi.x, lo.y, hi.y, bf[ni][0], bf[ni][1]);
            }
        }
    }

    const bool dorot = (wslot == 0 && zsel < 2);
    const float scl = (zsel == 0) ? QSCALE : 1.0f;

    #pragma unroll
    for (int mi = 0; mi < 4; mi++) {
        int r0 = blockIdx.y * 128 + wm + mi * 16 + g;
        int s0 = r0 & (NS - 1), s1 = (r0 + 8) & (NS - 1);
        #pragma unroll
        for (int ni = 0; ni < 4; ni++) {
            int col = blockIdx.x * 128 + wn + ni * 8 + tg * 2;
            float a0 = acc[mi][ni][0], a1 = acc[mi][ni][1];
            float a2 = acc[mi][ni][2], a3 = acc[mi][ni][3];
            if (wslot == 3) {
                float* Cf = (float*)C;
                *(float2*)(Cf + (size_t)r0 * ND + col)       = make_float2(a0, a1);
                *(float2*)(Cf + (size_t)(r0 + 8) * ND + col) = make_float2(a2, a3);
            } else if (dorot) {
                int pr = col >> 1;
                float2 t0 = g_rs[(size_t)s0 * 512 + pr];
                float2 t1 = g_rs[(size_t)s1 * 512 + pr];
                float n0 = (a0 * t0.x - a1 * t0.y) * scl;
                float n1 = (a0 * t0.y + a1 * t0.x) * scl;
                float n2 = (a2 * t1.x - a3 * t1.y) * scl;
                float n3 = (a2 * t1.y + a3 * t1.x) * scl;
                int p16 = pr & 7;
                int pp = ((p16 & 3) << 1) | (p16 >> 2);
                int wcol = (col & ~15) + 2 * pp;
                __half* Ch = (__half*)C;
                *(uint32_t*)(Ch + (size_t)r0 * ND + wcol)       = packh2(n0, n1);
                *(uint32_t*)(Ch + (size_t)(r0 + 8) * ND + wcol) = packh2(n2, n3);
            } else {   // V: natural fp16
                __half* Ch = (__half*)C;
                *(uint32_t*)(Ch + (size_t)r0 * ND + col)       = packh2(a0, a1);
                *(uint32_t*)(Ch + (size_t)(r0 + 8) * ND + col) = packh2(a2, a3);
            }
        }
    }
}

// ---------------------------------------------------------------------------
// Flash attention (unchanged): fp16 mma, no max-tracking, base-2 logits,
// 3-stage KV ring, P = ex2.f16x2(S), l via ones-column MMA, V ldmatrix.x4.trans
// ---------------------------------------------------------------------------
#define FQ  10240                  // halves: Q 128*80
#define FKB 5120                   // halves: K stage 64*80
#define FVB 4608                   // halves: V stage 64*72
#define FLASH_SMEM ((FQ + 3 * FKB + 3 * FVB) * 2)   // 78848 bytes

extern __shared__ __half fsh[];

__global__ __launch_bounds__(256, 2)
void flash_f16(const __half* __restrict__ Q, const __half* __restrict__ K,
               const __half* __restrict__ V, __half* __restrict__ O)
{
    __half* Qs  = fsh;
    __half* Ksb = fsh + FQ;
    __half* Vsb = fsh + FQ + 3 * FKB;

    const int tid = threadIdx.x;
    const int warp = tid >> 5, lane = tid & 31;
    const int g = lane >> 2, tg = lane & 3;
    const int qt = (int)gridDim.x - 1 - (int)blockIdx.x;
    const int bh = blockIdx.y;
    const int b = bh >> 4, h = bh & 15;
    const size_t base = (size_t)b * NS * ND + (size_t)h * NDK;
    const int q0 = qt * 128;
    const int wm = warp * 16;

    const int rq = tid >> 1, cq = (tid & 1) * 4;
    const int rk = tid >> 2, ck = (tid & 3) * 2;

    auto PREFKV = [&](int stage, int t) {
        __half* Ks = Ksb + stage * FKB;
        __half* Vs = Vsb + stage * FVB;
        int kn = 64 * t;
        #pragma unroll
        for (int p = 0; p < 2; p++) {
            cp_async16(&Ks[rk * 80 + (ck + p) * 8],
                       K + base + (size_t)(kn + rk) * ND + (ck + p) * 8);
            cp_async16(&Vs[rk * 72 + (ck + p) * 8],
                       V + base + (size_t)(kn + rk) * ND + (ck + p) * 8);
        }
        cp_commit();
    };

    #pragma unroll
    for (int p = 0; p < 4; p++)
        cp_async16(&Qs[rq * 80 + (cq + p) * 8],
                   Q + base + (size_t)(q0 + rq) * ND + (cq + p) * 8);
    {
        __half* Ks = Ksb; __half* Vs = Vsb;
        #pragma unroll
        for (int p = 0; p < 2; p++) {
            cp_async16(&Ks[rk * 80 + (ck + p) * 8],
                       K + base + (size_t)rk * ND + (ck + p) * 8);
            cp_async16(&Vs[rk * 72 + (ck + p) * 8],
                       V + base + (size_t)rk * ND + (ck + p) * 8);
        }
        cp_commit();
    }
    PREFKV(1, 1);

    const uint32_t vbase = smem_u32(Vsb) + (lane & 15) * 144 + (lane >> 4) * 16;

    float lacc[4] = {0.0f, 0.0f, 0.0f, 0.0f};
    float of[8][4];
    #pragma unroll
    for (int f = 0; f < 8; f++)
        #pragma unroll
        for (int rr = 0; rr < 4; rr++) of[f][rr] = 0.0f;

    uint32_t qf[4][4];

    const int nt = 2 * qt + 2;
    int stage = 0;
    for (int t = 0; t < nt; t++) {
        cp_wait1();
        __syncthreads();

        if (t == 0) {
            #pragma unroll
            for (int c = 0; c < 4; c++) {
                uint2 qlo = *(const uint2*)(&Qs[(wm + g) * 80 + c * 16 + 4 * tg]);
                uint2 qhi = *(const uint2*)(&Qs[(wm + g + 8) * 80 + c * 16 + 4 * tg]);
                qf[c][0] = qlo.x;  qf[c][2] = qlo.y;
                qf[c][1] = qhi.x;  qf[c][3] = qhi.y;
            }
        }

        if (t + 2 < nt) {
            int ns = stage + 2; if (ns >= 3) ns -= 3;
            PREFKV(ns, t + 2);
        }

        const __half* Kc = Ksb + stage * FKB;
        const int k0 = 64 * t;

        float sf[8][4];
        #pragma unroll
        for (int f = 0; f < 8; f++)
            #pragma unroll
            for (int rr = 0; rr < 4; rr++) sf[f][rr] = 0.0f;

        #pragma unroll
        for (int c = 0; c < 4; c++) {
            #pragma unroll
            for (int f = 0; f < 8; f++) {
                uint2 kb = *(const uint2*)(&Kc[(f * 8 + g) * 80 + c * 16 + 4 * tg]);
                mma_f16(sf[f][0], sf[f][1], sf[f][2], sf[f][3],
                        qf[c][0], qf[c][1], qf[c][2], qf[c][3], kb.x, kb.y);
            }
        }

        if (t >= 2 * qt) {
            int rlo = q0 + wm + g, rhi = rlo + 8;
            #pragma unroll
            for (int f = 0; f < 8; f++) {
                int col = k0 + f * 8 + tg * 2;
                if (col     > rlo) sf[f][0] = -INFINITY;
                if (col + 1 > rlo) sf[f][1] = -INFINITY;
                if (col     > rhi) sf[f][2] = -INFINITY;
                if (col + 1 > rhi) sf[f][3] = -INFINITY;
            }
        }

        const uint32_t vb = vbase + stage * (FVB * 2);
        #pragma unroll
        for (int c = 0; c < 4; c++) {
            uint32_t a0 = h2ex2(packh2(sf[2 * c][0],     sf[2 * c][1]));
            uint32_t a1 = h2ex2(packh2(sf[2 * c][2],     sf[2 * c][3]));
            uint32_t a2 = h2ex2(packh2(sf[2 * c + 1][0], sf[2 * c + 1][1]));
            uint32_t a3 = h2ex2(packh2(sf[2 * c + 1][2], sf[2 * c + 1][3]));
            mma_f16(lacc[0], lacc[1], lacc[2], lacc[3],
                    a0, a1, a2, a3, HONES, HONES);
            #pragma unroll
            for (int f2 = 0; f2 < 4; f2++) {
                uint32_t b00, b01, b10, b11;
                ldmatrix_x4_t(b00, b01, b10, b11, vb + c * 2304 + f2 * 32);
                mma_f16(of[2 * f2][0], of[2 * f2][1], of[2 * f2][2], of[2 * f2][3],
                        a0, a1, a2, a3, b00, b01);
                mma_f16(of[2 * f2 + 1][0], of[2 * f2 + 1][1],
                        of[2 * f2 + 1][2], of[2 * f2 + 1][3],
                        a0, a1, a2, a3, b10, b11);
            }
        }
        stage++; if (stage == 3) stage = 0;
    }

    float i0 = 1.0f / lacc[0], i1 = 1.0f / lacc[2];
    int rlo = q0 + wm + g;
    #pragma unroll
    for (int f = 0; f < 8; f++) {
        int pos = (f >> 1) * 16 + ((f & 1) ? 4 * tg + 2 : 4 * tg);
        *(uint32_t*)(O + base + (size_t)rlo * ND + pos) =
            packh2(of[f][0] * i0, of[f][1] * i0);
        *(uint32_t*)(O + base + (size_t)(rlo + 8) * ND + pos) =
            packh2(of[f][2] * i1, of[f][3] * i1);
    }
}

// ---------------------------------------------------------------------------
extern "C" void kernel_launch(void* const* d_in, const int* in_sizes, int n_in,
                              void* d_out, int out_size)
{
    const float* x  = (const float*)d_in[0];
    const float* Wq = (const float*)d_in[1];
    const float* Wk = (const float*)d_in[2];
    const float* Wv = (const float*)d_in[3];
    const float* Wo = (const float*)d_in[4];
    float* out = (float*)d_out;

    __half *pq, *pk, *pv, *pa, *pxh;
    cudaGetSymbolAddress((void**)&pq, g_q);
    cudaGetSymbolAddress((void**)&pk, g_k);
    cudaGetSymbolAddress((void**)&pv, g_v);
    cudaGetSymbolAddress((void**)&pa, g_attn);
    cudaGetSymbolAddress((void**)&pxh, g_xh);

    cudaFuncSetAttribute(gemm_f16, cudaFuncAttributeMaxDynamicSharedMemorySize, GEMM_SMEM);
    cudaFuncSetAttribute(flash_f16, cudaFuncAttributeMaxDynamicSharedMemorySize, FLASH_SMEM);

    prep_kernel<<<PREP_BLOCKS, 256>>>(x, Wq, Wk, Wv, Wo);

    // QKV fused (rope applied in epilogue for z=0,1; V natural)
    gemm_f16<<<dim3(8, 32, 3), 256, GEMM_SMEM>>>(pxh, 0, pq, pk, pv);

    flash_f16<<<dim3(NS / 128, NB * NH), 256, FLASH_SMEM>>>(pq, pk, pv, pa);

    // Output projection: float output
    gemm_f16<<<dim3(8, 32, 1), 256, GEMM_SMEM>>>(pa, 3, out, out, out);
}

// round 17
// speedup vs baseline: 1.2136x; 1.0235x over previous
#include <cuda_runtime.h>
#include <cuda_fp16.h>
#include <math.h>
#include <stdint.h>

#define NB 2
#define NS 2048
#define ND 1024
#define NH 16
#define NDK 64
#define NM (NB*NS)   // 4096

// Scratch (allocation-free)
__device__ __half g_q[(size_t)NM * ND];
__device__ __half g_k[(size_t)NM * ND];
__device__ __half g_v[(size_t)NM * ND];
__device__ __half g_attn[(size_t)NM * ND];
__device__ __half g_xh[(size_t)NM * ND];        // x, fp16, k-pair-permuted
__device__ __half g_wh[4 * (size_t)ND * ND];    // W^T, fp16, k-pair-permuted
__device__ float2 g_rs[(size_t)NS * 512];       // (cos,sin) per (spos, pair)

#define HONES  0x3C003C00u                      // half2 {1.0, 1.0}
#define QSCALE 0.1803368801111204f              // 0.125 * log2(e)

__device__ __forceinline__ uint32_t packh2(float lo, float hi)
{
    uint32_t r;
    asm("cvt.rn.f16x2.f32 %0, %1, %2;" : "=r"(r) : "f"(hi), "f"(lo));
    return r;
}

__device__ __forceinline__ uint32_t h2ex2(uint32_t x)
{
    uint32_t r;
    asm("ex2.approx.f16x2 %0, %1;" : "=r"(r) : "r"(x));
    return r;
}

__device__ __forceinline__ void mma_f16(float& d0, float& d1, float& d2, float& d3,
                                        uint32_t a0, uint32_t a1, uint32_t a2, uint32_t a3,
                                        uint32_t b0, uint32_t b1)
{
    asm volatile(
        "mma.sync.aligned.m16n8k16.row.col.f32.f16.f16.f32 "
        "{%0,%1,%2,%3}, {%4,%5,%6,%7}, {%8,%9}, {%0,%1,%2,%3};"
        : "+f"(d0), "+f"(d1), "+f"(d2), "+f"(d3)
        : "r"(a0), "r"(a1), "r"(a2), "r"(a3), "r"(b0), "r"(b1));
}

__device__ __forceinline__ void cp_async16(void* smem_dst, const void* gsrc)
{
    uint32_t s = (uint32_t)__cvta_generic_to_shared(smem_dst);
    asm volatile("cp.async.cg.shared.global [%0], [%1], 16;" :: "r"(s), "l"(gsrc));
}
__device__ __forceinline__ void cp_commit() { asm volatile("cp.async.commit_group;"); }
__device__ __forceinline__ void cp_wait1()  { asm volatile("cp.async.wait_group 1;"); }
__device__ __forceinline__ void cp_wait2()  { asm volatile("cp.async.wait_group 2;"); }

__device__ __forceinline__ uint32_t smem_u32(const void* p)
{
    uint32_t a;
    asm("{ .reg .u64 t; cvta.to.shared.u64 t, %1; cvt.u32.u64 %0, t; }" : "=r"(a) : "l"(p));
    return a;
}

__device__ __forceinline__ void ldmatrix_x4_t(uint32_t& r0, uint32_t& r1,
                                              uint32_t& r2, uint32_t& r3, uint32_t addr)
{
    asm volatile("ldmatrix.sync.aligned.m8n8.x4.trans.shared.b16 {%0, %1, %2, %3}, [%4];"
                 : "=r"(r0), "=r"(r1), "=r"(r2), "=r"(r3) : "r"(addr));
}

// ---------------------------------------------------------------------------
// Fused prep (one launch): x->fp16-permuted | 4x W transpose+cvt+permute | rope table
// ---------------------------------------------------------------------------
#define PREP_CVT_BLOCKS   1024
#define PREP_TW_BLOCKS    4096
#define PREP_RT_BLOCKS    4096
#define PREP_BLOCKS       (PREP_CVT_BLOCKS + PREP_TW_BLOCKS + PREP_RT_BLOCKS)

__global__ void prep_kernel(const float* __restrict__ x,
                            const float* w0, const float* w1,
                            const float* w2, const float* w3)
{
    __shared__ float t[32][33];
    const int bid = blockIdx.x;
    const int tid = threadIdx.x;

    if (bid < PREP_CVT_BLOCKS) {
        size_t i = ((size_t)bid * 256 + tid) * 16;
        float4 f0 = *(const float4*)(x + i);
        float4 f1 = *(const float4*)(x + i + 4);
        float4 f2 = *(const float4*)(x + i + 8);
        float4 f3 = *(const float4*)(x + i + 12);
        uint32_t o[8];
        o[0] = packh2(f0.x, f0.y);  o[1] = packh2(f2.x, f2.y);
        o[2] = packh2(f0.z, f0.w);  o[3] = packh2(f2.z, f2.w);
        o[4] = packh2(f1.x, f1.y);  o[5] = packh2(f3.x, f3.y);
        o[6] = packh2(f1.z, f1.w);  o[7] = packh2(f3.z, f3.w);
        *(uint4*)(&g_xh[i])     = make_uint4(o[0], o[1], o[2], o[3]);
        *(uint4*)(&g_xh[i + 8]) = make_uint4(o[4], o[5], o[6], o[7]);
    } else if (bid < PREP_CVT_BLOCKS + PREP_TW_BLOCKS) {
        int idx = bid - PREP_CVT_BLOCKS;
        int bx = idx & 31, by = (idx >> 5) & 31, bz = idx >> 10;
        const float* in = (bz == 0) ? w0 : (bz == 1) ? w1 : (bz == 2) ? w2 : w3;
        __half* outp = g_wh + (size_t)bz * ND * ND;
        int tx = tid & 31, ty = tid >> 5;
        int xg = bx * 32 + tx;
        int y0 = by * 32;
        #pragma unroll
        for (int i = ty; i < 32; i += 8)
            t[i][tx] = in[(size_t)(y0 + i) * ND + xg];
        __syncthreads();
        int ox = y0 + tx;
        int w16 = ox & 15, p = w16 >> 1, par = w16 & 1;
        int pox = (ox & ~15) | (((((p & 3) << 1) | (p >> 2)) << 1) | par);
        int oy0 = bx * 32;
        #pragma unroll
        for (int i = ty; i < 32; i += 8)
            outp[(size_t)(oy0 + i) * ND + pox] = __float2half_rn(t[tx][i]);
    } else {
        int i = (bid - PREP_CVT_BLOCKS - PREP_TW_BLOCKS) * 256 + tid;
        int spos = i >> 9, pr = i & 511;
        float freq = (float)exp(((double)(-2 * pr) / (double)ND) * 9.210340371976184);
        float ang = (float)spos * freq;
        double sd, cd;
        sincos((double)ang, &sd, &cd);
        g_rs[i] = make_float2((float)cd, (float)sd);
    }
}

// ---------------------------------------------------------------------------
// fp16 GEMM: 256 thr, 8 warps of 64x32, k-chunk 32, 4-stage ring, stride 48.
// R17 mainloop: fragments-first (critical path heads the chunk), cp.async
// issued in the LDS shadow, register double-buffered c-steps.
// ---------------------------------------------------------------------------
#define GST 48                      // halves per row
#define GAH (128*GST)               // 6144 halves: A stage
#define GSTAGE (2*GAH)              // 12288 halves per stage (A+B)
#define GEMM_SMEM (4 * GSTAGE * 2)  // 98304 bytes

__global__ __launch_bounds__(256, 2)
void gemm_f16(const __half* __restrict__ A, int wslot,
              void* C0, void* C1, void* C2)
{
    extern __shared__ __half gsmh[];

    const int tid = threadIdx.x;
    const int warp = tid >> 5, lane = tid & 31;
    const int g = lane >> 2, tg = lane & 3;
    const int wm = (warp >> 2) << 6;   // 0 or 64
    const int wn = (warp & 3) << 5;    // 0,32,64,96

    const int zsel = blockIdx.z;
    void* C = (zsel == 0) ? C0 : (zsel == 1) ? C1 : C2;
    const __half* Wt = g_wh + (size_t)(wslot + zsel) * ND * ND;
    const __half* Ab = A + (size_t)(blockIdx.y * 128) * ND;
    const __half* Bb = Wt + (size_t)(blockIdx.x * 128) * ND;

    float acc[4][4][4];
    #pragma unroll
    for (int mi = 0; mi < 4; mi++)
        #pragma unroll
        for (int ni = 0; ni < 4; ni++)
            #pragma unroll
            for (int r = 0; r < 4; r++) acc[mi][ni][r] = 0.0f;

    const int lr = tid >> 1;              // 0..127
    const int lq = (tid & 1) * 16;        // half offset within 32-half chunk

    auto PREF = [&](int stage, int k0) {
        __half* As = gsmh + stage * GSTAGE;
        __half* Bs = As + GAH;
        cp_async16(&As[lr * GST + lq],     Ab + (size_t)lr * ND + k0 + lq);
        cp_async16(&As[lr * GST + lq + 8], Ab + (size_t)lr * ND + k0 + lq + 8);
        cp_async16(&Bs[lr * GST + lq],     Bb + (size_t)lr * ND + k0 + lq);
        cp_async16(&Bs[lr * GST + lq + 8], Bb + (size_t)lr * ND + k0 + lq + 8);
        cp_commit();
    };

    PREF(0, 0); PREF(1, 32); PREF(2, 64);

    const int NKI = ND / 32;   // 32
    for (int i = 0; i < NKI; i++) {
        cp_wait2();
        __syncthreads();   // single barrier/chunk

        const __half* As = gsmh + (i & 3) * GSTAGE;
        const __half* Bs = As + GAH;

        // c0 fragments FIRST: start the critical path immediately
        uint32_t af[2][4][4], bf[2][4][2];
        #pragma unroll
        for (int ni = 0; ni < 4; ni++) {
            uint2 bb = *(const uint2*)(&Bs[(wn + ni * 8 + g) * GST + 4 * tg]);
            bf[0][ni][0] = bb.x;  bf[0][ni][1] = bb.y;
        }
        #pragma unroll
        for (int mi = 0; mi < 4; mi++) {
            uint2 lo = *(const uint2*)(&As[(wm + mi * 16 + g) * GST + 4 * tg]);
            uint2 hi = *(const uint2*)(&As[(wm + mi * 16 + g + 8) * GST + 4 * tg]);
            af[0][mi][0] = lo.x;  af[0][mi][2] = lo.y;
            af[0][mi][1] = hi.x;  af[0][mi][3] = hi.y;
        }

        // cp.async for chunk i+3 issues while c0 LDS results are in flight
        if (i + 3 < NKI) PREF((i + 3) & 3, (i + 3) * 32);

        // c1 fragments: latency hides under c0 MMAs below
        #pragma unroll
        for (int ni = 0; ni < 4; ni++) {
            uint2 bb = *(const uint2*)(&Bs[(wn + ni * 8 + g) * GST + 16 + 4 * tg]);
            bf[1][ni][0] = bb.x;  bf[1][ni][1] = bb.y;
        }
        #pragma unroll
        for (int mi = 0; mi < 4; mi++) {
            uint2 lo = *(const uint2*)(&As[(wm + mi * 16 + g) * GST + 16 + 4 * tg]);
            uint2 hi = *(const uint2*)(&As[(wm + mi * 16 + g + 8) * GST + 16 + 4 * tg]);
            af[1][mi][0] = lo.x;  af[1][mi][2] = lo.y;
            af[1][mi][1] = hi.x;  af[1][mi][3] = hi.y;
        }

        #pragma unroll
        for (int c = 0; c < 2; c++)
            #pragma unroll
            for (int mi = 0; mi < 4; mi++)
                #pragma unroll
                for (int ni = 0; ni < 4; ni++)
                    mma_f16(acc[mi][ni][0], acc[mi][ni][1], acc[mi][ni][2], acc[mi][ni][3],
                            af[c][mi][0], af[c][mi][1], af[c][mi][2], af[c][mi][3],
                            bf[c][ni][0], bf[c][ni][1]);
    }

    const bool dorot = (wslot == 0 && zsel < 2);
    const float scl = (zsel == 0) ? QSCALE : 1.0f;

    #pragma unroll
    for (int mi = 0; mi < 4; mi++) {
        int r0 = blockIdx.y * 128 + wm + mi * 16 + g;
        int s0 = r0 & (NS - 1), s1 = (r0 + 8) & (NS - 1);
        #pragma unroll
        for (int ni = 0; ni < 4; ni++) {
            int col = blockIdx.x * 128 + wn + ni * 8 + tg * 2;
            float a0 = acc[mi][ni][0], a1 = acc[mi][ni][1];
            float a2 = acc[mi][ni][2], a3 = acc[mi][ni][3];
            if (wslot == 3) {
                float* Cf = (float*)C;
                *(float2*)(Cf + (size_t)r0 * ND + col)       = make_float2(a0, a1);
                *(float2*)(Cf + (size_t)(r0 + 8) * ND + col) = make_float2(a2, a3);
            } else if (dorot) {
                int pr = col >> 1;
                float2 t0 = g_rs[(size_t)s0 * 512 + pr];
                float2 t1 = g_rs[(size_t)s1 * 512 + pr];
                float n0 = (a0 * t0.x - a1 * t0.y) * scl;
                float n1 = (a0 * t0.y + a1 * t0.x) * scl;
                float n2 = (a2 * t1.x - a3 * t1.y) * scl;
                float n3 = (a2 * t1.y + a3 * t1.x) * scl;
                int p16 = pr & 7;
                int pp = ((p16 & 3) << 1) | (p16 >> 2);
                int wcol = (col & ~15) + 2 * pp;
                __half* Ch = (__half*)C;
                *(uint32_t*)(Ch + (size_t)r0 * ND + wcol)       = packh2(n0, n1);
                *(uint32_t*)(Ch + (size_t)(r0 + 8) * ND + wcol) = packh2(n2, n3);
            } else {   // V: natural fp16
                __half* Ch = (__half*)C;
                *(uint32_t*)(Ch + (size_t)r0 * ND + col)       = packh2(a0, a1);
                *(uint32_t*)(Ch + (size_t)(r0 + 8) * ND + col) = packh2(a2, a3);
            }
        }
    }
}

// ---------------------------------------------------------------------------
// Flash attention (unchanged): fp16 mma, no max-tracking, base-2 logits,
// 3-stage KV ring, P = ex2.f16x2(S), l via ones-column MMA, V ldmatrix.x4.trans
// ---------------------------------------------------------------------------
#define FQ  10240                  // halves: Q 128*80
#define FKB 5120                   // halves: K stage 64*80
#define FVB 4608                   // halves: V stage 64*72
#define FLASH_SMEM ((FQ + 3 * FKB + 3 * FVB) * 2)   // 78848 bytes

extern __shared__ __half fsh[];

__global__ __launch_bounds__(256, 2)
void flash_f16(const __half* __restrict__ Q, const __half* __restrict__ K,
               const __half* __restrict__ V, __half* __restrict__ O)
{
    __half* Qs  = fsh;
    __half* Ksb = fsh + FQ;
    __half* Vsb = fsh + FQ + 3 * FKB;

    const int tid = threadIdx.x;
    const int warp = tid >> 5, lane = tid & 31;
    const int g = lane >> 2, tg = lane & 3;
    const int qt = (int)gridDim.x - 1 - (int)blockIdx.x;
    const int bh = blockIdx.y;
    const int b = bh >> 4, h = bh & 15;
    const size_t base = (size_t)b * NS * ND + (size_t)h * NDK;
    const int q0 = qt * 128;
    const int wm = warp * 16;

    const int rq = tid >> 1, cq = (tid & 1) * 4;
    const int rk = tid >> 2, ck = (tid & 3) * 2;

    auto PREFKV = [&](int stage, int t) {
        __half* Ks = Ksb + stage * FKB;
        __half* Vs = Vsb + stage * FVB;
        int kn = 64 * t;
        #pragma unroll
        for (int p = 0; p < 2; p++) {
            cp_async16(&Ks[rk * 80 + (ck + p) * 8],
                       K + base + (size_t)(kn + rk) * ND + (ck + p) * 8);
            cp_async16(&Vs[rk * 72 + (ck + p) * 8],
                       V + base + (size_t)(kn + rk) * ND + (ck + p) * 8);
        }
        cp_commit();
    };

    #pragma unroll
    for (int p = 0; p < 4; p++)
        cp_async16(&Qs[rq * 80 + (cq + p) * 8],
                   Q + base + (size_t)(q0 + rq) * ND + (cq + p) * 8);
    {
        __half* Ks = Ksb; __half* Vs = Vsb;
        #pragma unroll
        for (int p = 0; p < 2; p++) {
            cp_async16(&Ks[rk * 80 + (ck + p) * 8],
                       K + base + (size_t)rk * ND + (ck + p) * 8);
            cp_async16(&Vs[rk * 72 + (ck + p) * 8],
                       V + base + (size_t)rk * ND + (ck + p) * 8);
        }
        cp_commit();
    }
    PREFKV(1, 1);

    const uint32_t vbase = smem_u32(Vsb) + (lane & 15) * 144 + (lane >> 4) * 16;

    float lacc[4] = {0.0f, 0.0f, 0.0f, 0.0f};
    float of[8][4];
    #pragma unroll
    for (int f = 0; f < 8; f++)
        #pragma unroll
        for (int rr = 0; rr < 4; rr++) of[f][rr] = 0.0f;

    uint32_t qf[4][4];

    const int nt = 2 * qt + 2;
    int stage = 0;
    for (int t = 0; t < nt; t++) {
        cp_wait1();
        __syncthreads();

        if (t == 0) {
            #pragma unroll
            for (int c = 0; c < 4; c++) {
                uint2 qlo = *(const uint2*)(&Qs[(wm + g) * 80 + c * 16 + 4 * tg]);
                uint2 qhi = *(const uint2*)(&Qs[(wm + g + 8) * 80 + c * 16 + 4 * tg]);
                qf[c][0] = qlo.x;  qf[c][2] = qlo.y;
                qf[c][1] = qhi.x;  qf[c][3] = qhi.y;
            }
        }

        if (t + 2 < nt) {
            int ns = stage + 2; if (ns >= 3) ns -= 3;
            PREFKV(ns, t + 2);
        }

        const __half* Kc = Ksb + stage * FKB;
        const int k0 = 64 * t;

        float sf[8][4];
        #pragma unroll
        for (int f = 0; f < 8; f++)
            #pragma unroll
            for (int rr = 0; rr < 4; rr++) sf[f][rr] = 0.0f;

        #pragma unroll
        for (int c = 0; c < 4; c++) {
            #pragma unroll
            for (int f = 0; f < 8; f++) {
                uint2 kb = *(const uint2*)(&Kc[(f * 8 + g) * 80 + c * 16 + 4 * tg]);
                mma_f16(sf[f][0], sf[f][1], sf[f][2], sf[f][3],
                        qf[c][0], qf[c][1], qf[c][2], qf[c][3], kb.x, kb.y);
            }
        }

        if (t >= 2 * qt) {
            int rlo = q0 + wm + g, rhi = rlo + 8;
            #pragma unroll
            for (int f = 0; f < 8; f++) {
                int col = k0 + f * 8 + tg * 2;
                if (col     > rlo) sf[f][0] = -INFINITY;
                if (col + 1 > rlo) sf[f][1] = -INFINITY;
                if (col     > rhi) sf[f][2] = -INFINITY;
                if (col + 1 > rhi) sf[f][3] = -INFINITY;
            }
        }

        const uint32_t vb = vbase + stage * (FVB * 2);
        #pragma unroll
        for (int c = 0; c < 4; c++) {
            uint32_t a0 = h2ex2(packh2(sf[2 * c][0],     sf[2 * c][1]));
            uint32_t a1 = h2ex2(packh2(sf[2 * c][2],     sf[2 * c][3]));
            uint32_t a2 = h2ex2(packh2(sf[2 * c + 1][0], sf[2 * c + 1][1]));
            uint32_t a3 = h2ex2(packh2(sf[2 * c + 1][2], sf[2 * c + 1][3]));
            mma_f16(lacc[0], lacc[1], lacc[2], lacc[3],
                    a0, a1, a2, a3, HONES, HONES);
            #pragma unroll
            for (int f2 = 0; f2 < 4; f2++) {
                uint32_t b00, b01, b10, b11;
                ldmatrix_x4_t(b00, b01, b10, b11, vb + c * 2304 + f2 * 32);
                mma_f16(of[2 * f2][0], of[2 * f2][1], of[2 * f2][2], of[2 * f2][3],
                        a0, a1, a2, a3, b00, b01);
                mma_f16(of[2 * f2 + 1][0], of[2 * f2 + 1][1],
                        of[2 * f2 + 1][2], of[2 * f2 + 1][3],
                        a0, a1, a2, a3, b10, b11);
            }
        }
        stage++; if (stage == 3) stage = 0;
    }

    float i0 = 1.0f / lacc[0], i1 = 1.0f / lacc[2];
    int rlo = q0 + wm + g;
    #pragma unroll
    for (int f = 0; f < 8; f++) {
        int pos = (f >> 1) * 16 + ((f & 1) ? 4 * tg + 2 : 4 * tg);
        *(uint32_t*)(O + base + (size_t)rlo * ND + pos) =
            packh2(of[f][0] * i0, of[f][1] * i0);
        *(uint32_t*)(O + base + (size_t)(rlo + 8) * ND + pos) =
            packh2(of[f][2] * i1, of[f][3] * i1);
    }
}

// ---------------------------------------------------------------------------
extern "C" void kernel_launch(void* const* d_in, const int* in_sizes, int n_in,
                              void* d_out, int out_size)
{
    const float* x  = (const float*)d_in[0];
    const float* Wq = (const float*)d_in[1];
    const float* Wk = (const float*)d_in[2];
    const float* Wv = (const float*)d_in[3];
    const float* Wo = (const float*)d_in[4];
    float* out = (float*)d_out;

    __half *pq, *pk, *pv, *pa, *pxh;
    cudaGetSymbolAddress((void**)&pq, g_q);
    cudaGetSymbolAddress((void**)&pk, g_k);
    cudaGetSymbolAddress((void**)&pv, g_v);
    cudaGetSymbolAddress((void**)&pa, g_attn);
    cudaGetSymbolAddress((void**)&pxh, g_xh);

    cudaFuncSetAttribute(gemm_f16, cudaFuncAttributeMaxDynamicSharedMemorySize, GEMM_SMEM);
    cudaFuncSetAttribute(flash_f16, cudaFuncAttributeMaxDynamicSharedMemorySize, FLASH_SMEM);

    prep_kernel<<<PREP_BLOCKS, 256>>>(x, Wq, Wk, Wv, Wo);

    // QKV fused (rope applied in epilogue for z=0,1; V natural)
    gemm_f16<<<dim3(8, 32, 3), 256, GEMM_SMEM>>>(pxh, 0, pq, pk, pv);

    flash_f16<<<dim3(NS / 128, NB * NH), 256, FLASH_SMEM>>>(pq, pk, pv, pa);

    // Output projection: float output
    gemm_f16<<<dim3(8, 32, 1), 256, GEMM_SMEM>>>(pa, 3, out, out, out);
}